// round 6
// baseline (speedup 1.0000x reference)
#include <cuda_runtime.h>

#define N_NODES   100000
#define N_EDGES   1600000
#define NFEAT     48
#define HIDDEN    256
#define TPB       256
#define EPT       8                       // edges per thread (2x int4)
#define EDGE_THREADS (N_EDGES / EPT)                    // 200000
#define EDGE_BLOCKS  ((EDGE_THREADS + TPB - 1) / TPB)   // 782
#define NODE_BLOCKS  ((N_NODES + TPB - 1) / TPB)        // 391
#define NODE4        (N_NODES / 4)                      // 25000 (N divisible by 4)
#define NODE4_BLOCKS ((NODE4 + TPB - 1) / TPB)          // 98

// Scratch (device globals — zero-initialized at module load; g_deg is
// restored to all-zeros by k_final on EVERY call => identical start state
// each call: deterministic).
__device__ float g_deg[N_NODES];   // per-destination edge count
__device__ float g_dinv[N_NODES];  // rsqrt(deg+1)
__device__ float g_y[N_NODES];     // x @ (W1@W2)
__device__ float g_z[N_NODES];     // dinv * y
__device__ float g_s[N_NODES];     // z[c] + sum_{r->c} z[r]

// ---------------------------------------------------------------------------
// K1: blocks [0, EDGE_BLOCKS): degree histogram (8 edges/thread, RED only).
//     blocks [EDGE_BLOCKS, +NODE_BLOCKS): y = x . (W1@W2), with the 48-vector
//     weight fold done redundantly per block (L2-hit W1 reads, trivial cost).
//     The two halves use disjoint resources (L2 atomics vs DRAM stream) and
//     overlap inside one launch.
// ---------------------------------------------------------------------------
__global__ void __launch_bounds__(TPB) k_deg_y(const int*   __restrict__ ei,
                                               const float* __restrict__ x,
                                               const float* __restrict__ W1,
                                               const float* __restrict__ W2)
{
    if (blockIdx.x < EDGE_BLOCKS) {
        int tid = blockIdx.x * TPB + threadIdx.x;
        if (tid >= EDGE_THREADS) return;
        const int4* cols = reinterpret_cast<const int4*>(ei + N_EDGES);
        int4 a = cols[2 * tid + 0];
        int4 b = cols[2 * tid + 1];
        atomicAdd(&g_deg[a.x], 1.0f);
        atomicAdd(&g_deg[a.y], 1.0f);
        atomicAdd(&g_deg[a.z], 1.0f);
        atomicAdd(&g_deg[a.w], 1.0f);
        atomicAdd(&g_deg[b.x], 1.0f);
        atomicAdd(&g_deg[b.y], 1.0f);
        atomicAdd(&g_deg[b.z], 1.0f);
        atomicAdd(&g_deg[b.w], 1.0f);
        return;
    }

    // ---- node-dot blocks ----
    __shared__ float sW2[HIDDEN];
    __shared__ float sw[NFEAT];
    int t = threadIdx.x;
    sW2[t] = W2[t];
    __syncthreads();

    // per-block weight fold: 8 warps x 6 features, 256-length dots
    int warp = t >> 5, lane = t & 31;
    for (int f = warp; f < NFEAT; f += 8) {
        float p = 0.0f;
        #pragma unroll
        for (int h = lane; h < HIDDEN; h += 32)
            p += W1[f * HIDDEN + h] * sW2[h];
        #pragma unroll
        for (int o = 16; o; o >>= 1)
            p += __shfl_down_sync(0xffffffffu, p, o);
        if (lane == 0) sw[f] = p;
    }
    __syncthreads();

    int i = (blockIdx.x - EDGE_BLOCKS) * TPB + t;
    if (i >= N_NODES) return;
    const float4* xr = reinterpret_cast<const float4*>(x + (size_t)i * NFEAT);
    float acc = 0.0f;
    #pragma unroll
    for (int j = 0; j < NFEAT / 4; j++) {
        float4 v = xr[j];
        acc += v.x * sw[4 * j + 0] + v.y * sw[4 * j + 1]
             + v.z * sw[4 * j + 2] + v.w * sw[4 * j + 3];
    }
    g_y[i] = acc;
}

// ---------------------------------------------------------------------------
// K2: 4 nodes/thread: dinv = rsqrt(deg+1); z = dinv*y; s seeded with z.
// ---------------------------------------------------------------------------
__global__ void __launch_bounds__(TPB) k_init()
{
    int tid = blockIdx.x * TPB + threadIdx.x;
    if (tid >= NODE4) return;
    float4 d4 = reinterpret_cast<const float4*>(g_deg)[tid];
    float4 y4 = reinterpret_cast<const float4*>(g_y)[tid];
    float4 iv, z4;
    iv.x = rsqrtf(d4.x + 1.0f);  z4.x = iv.x * y4.x;
    iv.y = rsqrtf(d4.y + 1.0f);  z4.y = iv.y * y4.y;
    iv.z = rsqrtf(d4.z + 1.0f);  z4.z = iv.z * y4.z;
    iv.w = rsqrtf(d4.w + 1.0f);  z4.w = iv.w * y4.w;
    reinterpret_cast<float4*>(g_dinv)[tid] = iv;
    reinterpret_cast<float4*>(g_z)[tid]    = z4;
    reinterpret_cast<float4*>(g_s)[tid]    = z4;   // self-loop seed
}

// ---------------------------------------------------------------------------
// K3: edge scatter: s[c] += z[r]   (8 edges/thread)
// ---------------------------------------------------------------------------
__global__ void __launch_bounds__(TPB) k_edges(const int* __restrict__ ei)
{
    int tid = blockIdx.x * TPB + threadIdx.x;
    if (tid >= EDGE_THREADS) return;
    const int4* rows = reinterpret_cast<const int4*>(ei);
    const int4* cols = reinterpret_cast<const int4*>(ei + N_EDGES);
    int4 r0 = rows[2 * tid + 0];
    int4 r1 = rows[2 * tid + 1];
    int4 c0 = cols[2 * tid + 0];
    int4 c1 = cols[2 * tid + 1];

    float z0 = __ldg(&g_z[r0.x]);
    float z1 = __ldg(&g_z[r0.y]);
    float z2 = __ldg(&g_z[r0.z]);
    float z3 = __ldg(&g_z[r0.w]);
    float z4 = __ldg(&g_z[r1.x]);
    float z5 = __ldg(&g_z[r1.y]);
    float z6 = __ldg(&g_z[r1.z]);
    float z7 = __ldg(&g_z[r1.w]);

    atomicAdd(&g_s[c0.x], z0);
    atomicAdd(&g_s[c0.y], z1);
    atomicAdd(&g_s[c0.z], z2);
    atomicAdd(&g_s[c0.w], z3);
    atomicAdd(&g_s[c1.x], z4);
    atomicAdd(&g_s[c1.y], z5);
    atomicAdd(&g_s[c1.z], z6);
    atomicAdd(&g_s[c1.w], z7);
}

// ---------------------------------------------------------------------------
// K4: 4 nodes/thread: out = dinv*s + cterm; reset g_deg for next call.
//     cterm computed per-block from W2/bias/b2 (no serial dependency).
// ---------------------------------------------------------------------------
__global__ void __launch_bounds__(TPB) k_final(float* __restrict__ out,
                                               const float* __restrict__ bias,
                                               const float* __restrict__ W2,
                                               const float* __restrict__ b2)
{
    __shared__ float sred[TPB];
    int t = threadIdx.x;
    sred[t] = W2[t];
    __syncthreads();
    for (int s = TPB / 2; s > 0; s >>= 1) {
        if (t < s) sred[t] += sred[t + s];
        __syncthreads();
    }
    float cterm = bias[0] * sred[0] + b2[0];

    int tid = blockIdx.x * TPB + t;
    if (tid >= NODE4) return;
    float4 iv = reinterpret_cast<const float4*>(g_dinv)[tid];
    float4 s4 = reinterpret_cast<const float4*>(g_s)[tid];
    float4 o4;
    o4.x = fmaf(iv.x, s4.x, cterm);
    o4.y = fmaf(iv.y, s4.y, cterm);
    o4.z = fmaf(iv.z, s4.z, cterm);
    o4.w = fmaf(iv.w, s4.w, cterm);
    reinterpret_cast<float4*>(out)[tid] = o4;
    reinterpret_cast<float4*>(g_deg)[tid] = make_float4(0.f, 0.f, 0.f, 0.f);
}

// ---------------------------------------------------------------------------
extern "C" void kernel_launch(void* const* d_in, const int* in_sizes, int n_in,
                              void* d_out, int out_size)
{
    const float* x    = (const float*)d_in[0];   // [N, 48]
    const int*   ei   = (const int*)  d_in[1];   // [2, E]
    const float* W1   = (const float*)d_in[2];   // [48, 256]
    const float* bias = (const float*)d_in[3];   // [1]
    const float* W2   = (const float*)d_in[4];   // [256, 1]
    const float* b2   = (const float*)d_in[5];   // [1]
    float* out = (float*)d_out;                  // [N, 1]

    k_deg_y <<<EDGE_BLOCKS + NODE_BLOCKS, TPB>>>(ei, x, W1, W2);
    k_init  <<<NODE4_BLOCKS, TPB>>>();
    k_edges <<<EDGE_BLOCKS,  TPB>>>(ei);
    k_final <<<NODE4_BLOCKS, TPB>>>(out, bias, W2, b2);
}